// round 16
// baseline (speedup 1.0000x reference)
#include <cuda_runtime.h>
#include <cuda_fp16.h>
#include <math.h>

#define N_NODES 100000
#define N_EDGES 1600000
#define F_IN   128
#define H1     200
#define H1P    208   // K-padded: fp16 rows 416B, 16B-aligned
#define H2     50
#define H2P    56    // padded fp16 row: 112B
#define C_OUT  10
#define MAXDEG 128

typedef __half h16;

// ---------------- scratch -----------------------------------------------------
__device__ int   g_cnt[N_NODES];
__device__ int   g_bucket[(size_t)N_NODES * MAXDEG];
__device__ h16   g_xh  [(size_t)N_NODES * F_IN];
__device__ h16   g_a1h [(size_t)N_NODES * F_IN];
__device__ h16   g_h1h [(size_t)N_NODES * H1P];
__device__ h16   g_a2h [(size_t)N_NODES * H1P];
__device__ h16   g_h2h [(size_t)N_NODES * H2P];
// transposed single-plane fp16 weights [NN, Kpad]
__device__ h16   g_w1l[(size_t)H1 * F_IN], g_w1r[(size_t)H1 * F_IN];
__device__ h16   g_w2l[(size_t)H2 * H1P],  g_w2r[(size_t)H2 * H1P];

__device__ __forceinline__ unsigned packh2(h16 a, h16 b) {
    __half2 p = __halves2half2(a, b);
    return *reinterpret_cast<unsigned*>(&p);
}

// cp.async 16B with zero-fill when !ok
__device__ __forceinline__ void cp16(void* dst, const void* src, bool ok) {
    unsigned d = (unsigned)__cvta_generic_to_shared(dst);
    int ss = ok ? 16 : 0;
    asm volatile("cp.async.ca.shared.global [%0], [%1], 16, %2;"
                 :: "r"(d), "l"(src), "r"(ss));
}
__device__ __forceinline__ void cp_commit() {
    asm volatile("cp.async.commit_group;");
}
__device__ __forceinline__ void cp_wait1() {
    asm volatile("cp.async.wait_group 1;");
}

#define LDSM_X4(r0, r1, r2, r3, addr)                                         \
    asm volatile("ldmatrix.sync.aligned.m8n8.x4.shared.b16 {%0,%1,%2,%3}, [%4];" \
                 : "=r"(r0), "=r"(r1), "=r"(r2), "=r"(r3) : "r"(addr))

__device__ __forceinline__ unsigned sptr(const void* p) {
    return (unsigned)__cvta_generic_to_shared(p);
}

// ---------------- fused prep --------------------------------------------------
__global__ void prep_kernel(const float* __restrict__ x,
                            const float* __restrict__ Wl1,
                            const float* __restrict__ Wr1,
                            const float* __restrict__ Wl2,
                            const float* __restrict__ Wr2) {
    int i = blockIdx.x * blockDim.x + threadIdx.x;
    if (i < N_NODES) g_cnt[i] = 0;
    if (i < N_NODES * F_IN / 4) {           // x -> fp16
        float4 v = ((const float4*)x)[i];
        uint2 uo;
        uo.x = packh2(__float2half_rn(v.x), __float2half_rn(v.y));
        uo.y = packh2(__float2half_rn(v.z), __float2half_rn(v.w));
        *(uint2*)(g_xh + (size_t)i * 4) = uo;
    }
    if (i < H1 * F_IN) {                    // W1 l/r transposed fp16
        int n = i / F_IN, k = i - n * F_IN;
        g_w1l[i] = __float2half_rn(Wl1[(size_t)k * H1 + n]);
        g_w1r[i] = __float2half_rn(Wr1[(size_t)k * H1 + n]);
    }
    if (i < H2 * H1P) {                     // W2 l/r transposed fp16, padded
        int n = i / H1P, k = i - n * H1P;
        float vl = (k < H1) ? Wl2[(size_t)k * H2 + n] : 0.f;
        float vr = (k < H1) ? Wr2[(size_t)k * H2 + n] : 0.f;
        g_w2l[i] = __float2half_rn(vl);
        g_w2r[i] = __float2half_rn(vr);
    }
    if (i < N_NODES * 8) {                  // zero K-pads of h1h / a2h
        int node = i >> 3, kk = H1 + (i & 7);
        g_h1h[(size_t)node * H1P + kk] = __float2half_rn(0.f);
        g_a2h[(size_t)node * H1P + kk] = __float2half_rn(0.f);
    }
    if (i < N_NODES * 6) {                  // zero pads of h2h
        int node = i / 6, kk = H2 + (i - node * 6);
        g_h2h[(size_t)node * H2P + kk] = __float2half_rn(0.f);
    }
}

// ---------------- bucket build ------------------------------------------------
__global__ void bucket_build_kernel(const int* __restrict__ src,
                                    const int* __restrict__ dst) {
    int e = blockIdx.x * blockDim.x + threadIdx.x;
    if (e >= N_EDGES) return;
    int d = dst[e];
    int p = atomicAdd(&g_cnt[d], 1);
    if (p < MAXDEG) g_bucket[(size_t)d * MAXDEG + p] = src[e];
}

// ---------------- fp16 aggregation (max is rounding-commutative) -------------
__device__ __forceinline__ void hmax2_acc(uint2& m, uint2 v) {
    __half2* mp = (__half2*)&m;
    const __half2* vp = (const __half2*)&v;
    mp[0] = __hmax2(mp[0], vp[0]);
    mp[1] = __hmax2(mp[1], vp[1]);
}

// gather fp16 rows (stride STR halves), emit fp16 max (stride STR); F<=STR
template <int F, int STR>
__global__ void agg_h16_kernel(const h16* __restrict__ x, h16* __restrict__ o) {
    constexpr int C4 = (F + 3) / 4;
    constexpr int RV = (C4 + 31) / 32;

    int gwarp = (blockIdx.x * blockDim.x + threadIdx.x) >> 5;
    int lane  = threadIdx.x & 31;
    if (gwarp >= N_NODES) return;

    int c = g_cnt[gwarp];
    if (c > MAXDEG) c = MAXDEG;

    uint2 m[RV];
    {
        h16 ninf = __float2half(-INFINITY);
        unsigned nn = packh2(ninf, ninf);
#pragma unroll
        for (int r = 0; r < RV; r++) { m[r].x = nn; m[r].y = nn; }
    }

    const int* bk = g_bucket + (size_t)gwarp * MAXDEG;
    int i = 0;
    for (; i + 3 < c; i += 4) {
        int s0 = bk[i], s1 = bk[i + 1], s2 = bk[i + 2], s3 = bk[i + 3];
        const uint2* p0 = (const uint2*)(x + (size_t)s0 * STR);
        const uint2* p1 = (const uint2*)(x + (size_t)s1 * STR);
        const uint2* p2 = (const uint2*)(x + (size_t)s2 * STR);
        const uint2* p3 = (const uint2*)(x + (size_t)s3 * STR);
#pragma unroll
        for (int r = 0; r < RV; r++) {
            int ch = lane + r * 32;
            if (ch < C4) {
                uint2 v0 = p0[ch], v1 = p1[ch], v2 = p2[ch], v3 = p3[ch];
                hmax2_acc(v0, v1); hmax2_acc(v2, v3);
                hmax2_acc(v0, v2);
                hmax2_acc(m[r], v0);
            }
        }
    }
    for (; i < c; i++) {
        const uint2* p0 = (const uint2*)(x + (size_t)bk[i] * STR);
#pragma unroll
        for (int r = 0; r < RV; r++) {
            int ch = lane + r * 32;
            if (ch < C4) hmax2_acc(m[r], p0[ch]);
        }
    }

    uint2* out = (uint2*)(o + (size_t)gwarp * STR);
#pragma unroll
    for (int r = 0; r < RV; r++) {
        int ch = lane + r * 32;
        if (ch < C4) out[ch] = (c == 0) ? make_uint2(0u, 0u) : m[r];
    }
}

// ---------------- plain fp16 tensor-core dual GEMM ---------------------------
#define MMAF16(d, a, b0, b1)                                                  \
    asm volatile(                                                             \
        "mma.sync.aligned.m16n8k16.row.col.f32.f16.f16.f32 "                  \
        "{%0,%1,%2,%3}, {%4,%5,%6,%7}, {%8,%9}, {%0,%1,%2,%3};"               \
        : "+f"(d[0]), "+f"(d[1]), "+f"(d[2]), "+f"(d[3])                      \
        : "r"(a[0]), "r"(a[1]), "r"(a[2]), "r"(a[3]), "r"(b0), "r"(b1))

// out = (A1@W1 + A2@W2 + bias) as fp16 rows of stride ostride.
// BM=128 (WM=4), BN=WN*NT*8, 256 threads, 3-stage cp.async, ldmatrix frags.
// KB = K-tile depth (16 or 32); K must be a multiple of KB per matrix.
template <int WN, int NT, int OCC, int KB>
__global__ __launch_bounds__(256, OCC)
void gemm_s(const h16* __restrict__ A1, const h16* __restrict__ A2,
            const h16* __restrict__ B1, const h16* __restrict__ B2,
            const float* __restrict__ bias,
            h16* __restrict__ outh,
            int M, int K, int NN, int ostride) {
    constexpr int WM = 4;
    constexpr int BM = 128;
    constexpr int BN = WN * NT * 8;
    constexpr int LDSTR = KB + 8;
    constexpr int ST = 3;
    constexpr int NC = KB / 16;
    static_assert(WM * WN == 8 && NT % 2 == 0, "bad tile config");

    extern __shared__ __align__(16) char smem_raw[];
    h16* Ash = (h16*)smem_raw;                  // ST * BM * LDSTR
    h16* Bsh = Ash + ST * BM * LDSTR;           // ST * BN * LDSTR

    int tid = threadIdx.x;
    int lane = tid & 31;
    int wid = tid >> 5;
    int wm = wid % WM;
    int wn = wid / WM;
    int g  = lane >> 2;
    int tg = lane & 3;
    int lr = lane & 15;
    int lc = (lane >> 4) * 8;

    int rowBase = blockIdx.y * BM;
    int colBase = blockIdx.x * BN;

    int npt  = K / KB;
    int totT = 2 * npt;

    const int r_  = tid >> 1;
    const int kh_ = (tid & 1) * (KB / 2);
    const int aRow = rowBase + r_;
    const bool doB = r_ < BN;
    const int gN   = colBase + r_;

    float acc[2][NT][4];
#pragma unroll
    for (int mt = 0; mt < 2; mt++)
#pragma unroll
        for (int nt = 0; nt < NT; nt++)
#pragma unroll
            for (int q = 0; q < 4; q++) acc[mt][nt][q] = 0.f;

    auto issue = [&](int t, int s) {
        const h16 *A, *B; int ko;
        if (t < npt) { A = A1; B = B1; ko = t * KB; }
        else         { A = A2; B = B2; ko = (t - npt) * KB; }
        int gk = ko + kh_;
        bool okA = aRow < M;
#pragma unroll
        for (int cc = 0; cc < NC; cc++)
            cp16(&Ash[s * BM * LDSTR + r_ * LDSTR + kh_ + cc * 8],
                 okA ? (A + (size_t)aRow * K + gk + cc * 8) : A, okA);
        if (doB) {
            bool okB = gN < NN;
#pragma unroll
            for (int cc = 0; cc < NC; cc++)
                cp16(&Bsh[s * BN * LDSTR + r_ * LDSTR + kh_ + cc * 8],
                     okB ? (B + (size_t)gN * K + gk + cc * 8) : B, okB);
        }
    };

    auto compute = [&](int s) {
        const h16* As = Ash + s * BM * LDSTR;
        const h16* Bs = Bsh + s * BN * LDSTR;

#pragma unroll
        for (int ks = 0; ks < NC; ks++) {
            int kc = lc + ks * 16;
            unsigned af[2][4];
#pragma unroll
            for (int mt = 0; mt < 2; mt++) {
                int r0 = wm * 32 + mt * 16 + lr;
                LDSM_X4(af[mt][0], af[mt][1], af[mt][2], af[mt][3],
                        sptr(&As[r0 * LDSTR + kc]));
            }
#pragma unroll
            for (int p = 0; p < NT / 2; p++) {
                int rowb = (wn * NT + 2 * p) * 8 + lr;
                unsigned b0, b1, b2, b3;
                LDSM_X4(b0, b1, b2, b3, sptr(&Bs[rowb * LDSTR + kc]));
                MMAF16(acc[0][2 * p],     af[0], b0, b2);
                MMAF16(acc[1][2 * p],     af[1], b0, b2);
                MMAF16(acc[0][2 * p + 1], af[0], b1, b3);
                MMAF16(acc[1][2 * p + 1], af[1], b1, b3);
            }
        }
    };

    issue(0, 0); cp_commit();
    if (totT > 1) issue(1, 1);
    cp_commit();

    for (int t = 0; t < totT; t++) {
        cp_wait1();
        __syncthreads();
        if (t + 2 < totT) issue(t + 2, (t + 2) % ST);
        cp_commit();
        compute(t % ST);
    }

    // ---- epilogue: bias add, fp16 store ----
#pragma unroll
    for (int mt = 0; mt < 2; mt++) {
#pragma unroll
        for (int nt = 0; nt < NT; nt++) {
            int col = colBase + (wn * NT + nt) * 8 + 2 * tg;
            if (col >= NN) continue;
            float2 bv = *(const float2*)(bias + col);
            int row0 = rowBase + wm * 32 + mt * 16 + g;
            int row1 = row0 + 8;
            if (row0 < M)
                *(unsigned*)(outh + (size_t)row0 * ostride + col) =
                    packh2(__float2half_rn(acc[mt][nt][0] + bv.x),
                           __float2half_rn(acc[mt][nt][1] + bv.y));
            if (row1 < M)
                *(unsigned*)(outh + (size_t)row1 * ostride + col) =
                    packh2(__float2half_rn(acc[mt][nt][2] + bv.x),
                           __float2half_rn(acc[mt][nt][3] + bv.y));
        }
    }
}

// ---------------- fused layer-3: aggregation + matvec + log_softmax ----------
// Warp per node: gather h2h neighbor maxes into registers (lane = 4-half
// chunk), per-lane partial logits, shfl reduction, softmax in lane 0.
__global__ void agg3_final_kernel(const h16* __restrict__ h2h,
                                  const float* __restrict__ Wl,
                                  const float* __restrict__ Wr,
                                  const float* __restrict__ b,
                                  float* __restrict__ out) {
    constexpr int C4 = H2P / 4;    // 14 chunks
    __shared__ float sWl[H2 * C_OUT], sWr[H2 * C_OUT], sb[C_OUT];
    for (int i = threadIdx.x; i < H2 * C_OUT; i += blockDim.x) {
        sWl[i] = Wl[i];
        sWr[i] = Wr[i];
    }
    if (threadIdx.x < C_OUT) sb[threadIdx.x] = b[threadIdx.x];
    __syncthreads();

    int warp = threadIdx.x >> 5;
    int lane = threadIdx.x & 31;
    int n = blockIdx.x * 8 + warp;
    if (n >= N_NODES) return;

    int c = g_cnt[n];
    if (c > MAXDEG) c = MAXDEG;

    uint2 m;
    {
        h16 ninf = __float2half(-INFINITY);
        unsigned nn = packh2(ninf, ninf);
        m.x = nn; m.y = nn;
    }

    const int* bk = g_bucket + (size_t)n * MAXDEG;
    int i = 0;
    for (; i + 3 < c; i += 4) {
        int s0 = bk[i], s1 = bk[i + 1], s2 = bk[i + 2], s3 = bk[i + 3];
        if (lane < C4) {
            uint2 v0 = ((const uint2*)(h2h + (size_t)s0 * H2P))[lane];
            uint2 v1 = ((const uint2*)(h2h + (size_t)s1 * H2P))[lane];
            uint2 v2 = ((const uint2*)(h2h + (size_t)s2 * H2P))[lane];
            uint2 v3 = ((const uint2*)(h2h + (size_t)s3 * H2P))[lane];
            hmax2_acc(v0, v1); hmax2_acc(v2, v3);
            hmax2_acc(v0, v2);
            hmax2_acc(m, v0);
        }
    }
    for (; i < c; i++) {
        if (lane < C4) {
            uint2 v0 = ((const uint2*)(h2h + (size_t)bk[i] * H2P))[lane];
            hmax2_acc(m, v0);
        }
    }

    float logit[C_OUT];
#pragma unroll
    for (int j = 0; j < C_OUT; j++) logit[j] = 0.f;

    if (lane < C4) {
        uint2 hv = ((const uint2*)(h2h + (size_t)n * H2P))[lane];
        float a[4], h[4];
        {
            float2 f0 = __half22float2(*(const __half2*)&m.x);
            float2 f1 = __half22float2(*(const __half2*)&m.y);
            a[0] = f0.x; a[1] = f0.y; a[2] = f1.x; a[3] = f1.y;
            float2 g0 = __half22float2(*(const __half2*)&hv.x);
            float2 g1 = __half22float2(*(const __half2*)&hv.y);
            h[0] = g0.x; h[1] = g0.y; h[2] = g1.x; h[3] = g1.y;
        }
        if (c == 0) { a[0] = a[1] = a[2] = a[3] = 0.f; }
        int kb = lane * 4;
#pragma unroll
        for (int q = 0; q < 4; q++) {
            int k = kb + q;
            if (k < H2) {
#pragma unroll
                for (int j = 0; j < C_OUT; j++)
                    logit[j] += a[q] * sWl[k * C_OUT + j] +
                                h[q] * sWr[k * C_OUT + j];
            }
        }
    }

    // warp reduction
#pragma unroll
    for (int off = 16; off > 0; off >>= 1)
#pragma unroll
        for (int j = 0; j < C_OUT; j++)
            logit[j] += __shfl_xor_sync(0xffffffffu, logit[j], off);

    if (lane == 0) {
#pragma unroll
        for (int j = 0; j < C_OUT; j++) logit[j] += sb[j];
        float mx = logit[0];
#pragma unroll
        for (int j = 1; j < C_OUT; j++) mx = fmaxf(mx, logit[j]);
        float s = 0.f;
#pragma unroll
        for (int j = 0; j < C_OUT; j++) s += expf(logit[j] - mx);
        float lse = mx + logf(s);
#pragma unroll
        for (int j = 0; j < C_OUT; j++)
            out[(size_t)n * C_OUT + j] = logit[j] - lse;
    }
}

// ---------------- launch ------------------------------------------------------
extern "C" void kernel_launch(void* const* d_in, const int* in_sizes, int n_in,
                              void* d_out, int out_size) {
    const float* x    = (const float*)d_in[0];
    const int*   ei   = (const int*)d_in[1];
    const float* W_l1 = (const float*)d_in[2];
    const float* b1   = (const float*)d_in[3];
    const float* W_r1 = (const float*)d_in[4];
    const float* W_l2 = (const float*)d_in[5];
    const float* b2   = (const float*)d_in[6];
    const float* W_r2 = (const float*)d_in[7];
    const float* W_l3 = (const float*)d_in[8];
    const float* b3   = (const float*)d_in[9];
    const float* W_r3 = (const float*)d_in[10];
    float* out = (float*)d_out;

    const int* src = ei;
    const int* dst = ei + N_EDGES;

    h16 *xh, *a1h, *h1h, *a2h, *h2h, *w1l, *w1r, *w2l, *w2r;
    cudaGetSymbolAddress((void**)&xh,  g_xh);
    cudaGetSymbolAddress((void**)&a1h, g_a1h);
    cudaGetSymbolAddress((void**)&h1h, g_h1h);
    cudaGetSymbolAddress((void**)&a2h, g_a2h);
    cudaGetSymbolAddress((void**)&h2h, g_h2h);
    cudaGetSymbolAddress((void**)&w1l, g_w1l);
    cudaGetSymbolAddress((void**)&w1r, g_w1r);
    cudaGetSymbolAddress((void**)&w2l, g_w2l);
    cudaGetSymbolAddress((void**)&w2r, g_w2r);

    // smem: ST * (BM + BN) * (KB+8) * 2 bytes
    const int SMEM1 = 3 * (128 + 64) * 40 * 2;    // 46080 (KB=32, BN=64)
    const int SMEM2 = 3 * (128 + 64) * 24 * 2;    // 27648 (KB=16, BN=64)
    cudaFuncSetAttribute(gemm_s<2, 4, 3, 32>,
                         cudaFuncAttributeMaxDynamicSharedMemorySize, SMEM1);
    cudaFuncSetAttribute(gemm_s<2, 4, 3, 16>,
                         cudaFuncAttributeMaxDynamicSharedMemorySize, SMEM2);

    prep_kernel<<<(N_NODES * F_IN / 4 + 255) / 256, 256>>>(x, W_l1, W_r1,
                                                           W_l2, W_r2);
    bucket_build_kernel<<<(N_EDGES + 255) / 256, 256>>>(src, dst);

    const int aggBlocks = (N_NODES * 32 + 255) / 256;

    // layer 1: agg over xh -> a1h; GEMM (BM=128, BN=64, KB=32, occ 3) -> h1h
    agg_h16_kernel<F_IN, F_IN><<<aggBlocks, 256>>>(xh, a1h);
    {
        dim3 grid((H1 + 63) / 64, (N_NODES + 127) / 128);
        gemm_s<2, 4, 3, 32><<<grid, 256, SMEM1>>>(
            a1h, xh, w1l, w1r, b1, h1h, N_NODES, F_IN, H1, H1P);
    }

    // layer 2: agg over h1h -> a2h; GEMM (BM=128, BN=64, KB=16, occ 3) -> h2h
    agg_h16_kernel<H1, H1P><<<aggBlocks, 256>>>(h1h, a2h);
    {
        dim3 grid(1, (N_NODES + 127) / 128);
        gemm_s<2, 4, 3, 16><<<grid, 256, SMEM2>>>(
            a2h, h1h, w2l, w2r, b2, h2h, N_NODES, H1P, H2, H2P);
    }

    // layer 3: fused aggregation + final matvec + log_softmax
    agg3_final_kernel<<<(N_NODES + 7) / 8, 256>>>(h2h, W_l3, W_r3, b3, out);
}

// round 17
// speedup vs baseline: 1.1486x; 1.1486x over previous
#include <cuda_runtime.h>
#include <cuda_fp16.h>
#include <math.h>

#define N_NODES 100000
#define N_EDGES 1600000
#define F_IN   128
#define H1     200
#define H1P    208   // K-padded: fp16 rows 416B, 16B-aligned
#define H2     50
#define H2P    56    // padded fp16 row: 112B
#define C_OUT  10
#define MAXDEG 128

typedef __half h16;

// ---------------- scratch -----------------------------------------------------
__device__ int   g_cnt[N_NODES];
__device__ int   g_bucket[(size_t)N_NODES * MAXDEG];
__device__ __align__(16) h16 g_xh  [(size_t)N_NODES * F_IN];
__device__ __align__(16) h16 g_a1h [(size_t)N_NODES * F_IN];
__device__ __align__(16) h16 g_h1h [(size_t)N_NODES * H1P];
__device__ __align__(16) h16 g_a2h [(size_t)N_NODES * H1P];
__device__ __align__(16) h16 g_h2h [(size_t)N_NODES * H2P];
__device__ __align__(16) h16 g_a3h [(size_t)N_NODES * H2P];
// transposed single-plane fp16 weights [NN, Kpad]
__device__ __align__(16) h16 g_w1l[(size_t)H1 * F_IN], g_w1r[(size_t)H1 * F_IN];
__device__ __align__(16) h16 g_w2l[(size_t)H2 * H1P],  g_w2r[(size_t)H2 * H1P];

__device__ __forceinline__ unsigned packh2(h16 a, h16 b) {
    __half2 p = __halves2half2(a, b);
    return *reinterpret_cast<unsigned*>(&p);
}

// cp.async 16B with zero-fill when !ok
__device__ __forceinline__ void cp16(void* dst, const void* src, bool ok) {
    unsigned d = (unsigned)__cvta_generic_to_shared(dst);
    int ss = ok ? 16 : 0;
    asm volatile("cp.async.ca.shared.global [%0], [%1], 16, %2;"
                 :: "r"(d), "l"(src), "r"(ss));
}
__device__ __forceinline__ void cp_commit() {
    asm volatile("cp.async.commit_group;");
}
template <int N>
__device__ __forceinline__ void cp_wait() {
    asm volatile("cp.async.wait_group %0;" :: "n"(N));
}

#define LDSM_X4(r0, r1, r2, r3, addr)                                         \
    asm volatile("ldmatrix.sync.aligned.m8n8.x4.shared.b16 {%0,%1,%2,%3}, [%4];" \
                 : "=r"(r0), "=r"(r1), "=r"(r2), "=r"(r3) : "r"(addr))

__device__ __forceinline__ unsigned sptr(const void* p) {
    return (unsigned)__cvta_generic_to_shared(p);
}

// ---------------- fused prep --------------------------------------------------
__global__ void prep_kernel(const float* __restrict__ x,
                            const float* __restrict__ Wl1,
                            const float* __restrict__ Wr1,
                            const float* __restrict__ Wl2,
                            const float* __restrict__ Wr2) {
    int i = blockIdx.x * blockDim.x + threadIdx.x;
    if (i < N_NODES) g_cnt[i] = 0;
    if (i < N_NODES * F_IN / 4) {           // x -> fp16
        float4 v = ((const float4*)x)[i];
        uint2 uo;
        uo.x = packh2(__float2half_rn(v.x), __float2half_rn(v.y));
        uo.y = packh2(__float2half_rn(v.z), __float2half_rn(v.w));
        *(uint2*)(g_xh + (size_t)i * 4) = uo;
    }
    if (i < H1 * F_IN) {                    // W1 l/r transposed fp16
        int n = i / F_IN, k = i - n * F_IN;
        g_w1l[i] = __float2half_rn(Wl1[(size_t)k * H1 + n]);
        g_w1r[i] = __float2half_rn(Wr1[(size_t)k * H1 + n]);
    }
    if (i < H2 * H1P) {                     // W2 l/r transposed fp16, padded
        int n = i / H1P, k = i - n * H1P;
        float vl = (k < H1) ? Wl2[(size_t)k * H2 + n] : 0.f;
        float vr = (k < H1) ? Wr2[(size_t)k * H2 + n] : 0.f;
        g_w2l[i] = __float2half_rn(vl);
        g_w2r[i] = __float2half_rn(vr);
    }
    if (i < N_NODES * 8) {                  // zero K-pads of h1h / a2h
        int node = i >> 3, kk = H1 + (i & 7);
        g_h1h[(size_t)node * H1P + kk] = __float2half_rn(0.f);
        g_a2h[(size_t)node * H1P + kk] = __float2half_rn(0.f);
    }
    if (i < N_NODES * 6) {                  // zero pads of h2h
        int node = i / 6, kk = H2 + (i - node * 6);
        g_h2h[(size_t)node * H2P + kk] = __float2half_rn(0.f);
    }
}

// ---------------- bucket build ------------------------------------------------
__global__ void bucket_build_kernel(const int* __restrict__ src,
                                    const int* __restrict__ dst) {
    int e = blockIdx.x * blockDim.x + threadIdx.x;
    if (e >= N_EDGES) return;
    int d = dst[e];
    int p = atomicAdd(&g_cnt[d], 1);
    if (p < MAXDEG) g_bucket[(size_t)d * MAXDEG + p] = src[e];
}

// ---------------- fp16 aggregation (max is rounding-commutative) -------------
__device__ __forceinline__ void hmax2_acc(uint2& m, uint2 v) {
    __half2* mp = (__half2*)&m;
    const __half2* vp = (const __half2*)&v;
    mp[0] = __hmax2(mp[0], vp[0]);
    mp[1] = __hmax2(mp[1], vp[1]);
}
__device__ __forceinline__ void hmax4_acc(uint4& m, uint4 v) {
    __half2* mp = (__half2*)&m;
    const __half2* vp = (const __half2*)&v;
    mp[0] = __hmax2(mp[0], vp[0]);
    mp[1] = __hmax2(mp[1], vp[1]);
    mp[2] = __hmax2(mp[2], vp[2]);
    mp[3] = __hmax2(mp[3], vp[3]);
}

// gather fp16 rows (stride STR halves), emit fp16 max (stride STR); F<=STR
template <int F, int STR>
__global__ void agg_h16_kernel(const h16* __restrict__ x, h16* __restrict__ o) {
    constexpr int C4 = (F + 3) / 4;
    constexpr int RV = (C4 + 31) / 32;

    int gwarp = (blockIdx.x * blockDim.x + threadIdx.x) >> 5;
    int lane  = threadIdx.x & 31;
    if (gwarp >= N_NODES) return;

    int c = g_cnt[gwarp];
    if (c > MAXDEG) c = MAXDEG;

    uint2 m[RV];
    {
        h16 ninf = __float2half(-INFINITY);
        unsigned nn = packh2(ninf, ninf);
#pragma unroll
        for (int r = 0; r < RV; r++) { m[r].x = nn; m[r].y = nn; }
    }

    const int* bk = g_bucket + (size_t)gwarp * MAXDEG;
    int i = 0;
    for (; i + 3 < c; i += 4) {
        int s0 = bk[i], s1 = bk[i + 1], s2 = bk[i + 2], s3 = bk[i + 3];
        const uint2* p0 = (const uint2*)(x + (size_t)s0 * STR);
        const uint2* p1 = (const uint2*)(x + (size_t)s1 * STR);
        const uint2* p2 = (const uint2*)(x + (size_t)s2 * STR);
        const uint2* p3 = (const uint2*)(x + (size_t)s3 * STR);
#pragma unroll
        for (int r = 0; r < RV; r++) {
            int ch = lane + r * 32;
            if (ch < C4) {
                uint2 v0 = p0[ch], v1 = p1[ch], v2 = p2[ch], v3 = p3[ch];
                hmax2_acc(v0, v1); hmax2_acc(v2, v3);
                hmax2_acc(v0, v2);
                hmax2_acc(m[r], v0);
            }
        }
    }
    for (; i < c; i++) {
        const uint2* p0 = (const uint2*)(x + (size_t)bk[i] * STR);
#pragma unroll
        for (int r = 0; r < RV; r++) {
            int ch = lane + r * 32;
            if (ch < C4) hmax2_acc(m[r], p0[ch]);
        }
    }

    uint2* out = (uint2*)(o + (size_t)gwarp * STR);
#pragma unroll
    for (int r = 0; r < RV; r++) {
        int ch = lane + r * 32;
        if (ch < C4) out[ch] = (c == 0) ? make_uint2(0u, 0u) : m[r];
    }
}

// uint4 (LDG.128) variant: F multiple of 8, F/8 <= 32 lanes. Used for agg2.
template <int F, int STR>
__global__ void agg_h16x4_kernel(const h16* __restrict__ x,
                                 h16* __restrict__ o) {
    constexpr int C8 = F / 8;
    static_assert(F % 8 == 0 && C8 <= 32, "bad F for x4 agg");

    int gwarp = (blockIdx.x * blockDim.x + threadIdx.x) >> 5;
    int lane  = threadIdx.x & 31;
    if (gwarp >= N_NODES) return;

    int c = g_cnt[gwarp];
    if (c > MAXDEG) c = MAXDEG;

    uint4 m;
    {
        h16 ninf = __float2half(-INFINITY);
        unsigned nn = packh2(ninf, ninf);
        m.x = nn; m.y = nn; m.z = nn; m.w = nn;
    }

    const int* bk = g_bucket + (size_t)gwarp * MAXDEG;
    int i = 0;
    for (; i + 3 < c; i += 4) {
        int s0 = bk[i], s1 = bk[i + 1], s2 = bk[i + 2], s3 = bk[i + 3];
        if (lane < C8) {
            uint4 v0 = ((const uint4*)(x + (size_t)s0 * STR))[lane];
            uint4 v1 = ((const uint4*)(x + (size_t)s1 * STR))[lane];
            uint4 v2 = ((const uint4*)(x + (size_t)s2 * STR))[lane];
            uint4 v3 = ((const uint4*)(x + (size_t)s3 * STR))[lane];
            hmax4_acc(v0, v1); hmax4_acc(v2, v3);
            hmax4_acc(v0, v2);
            hmax4_acc(m, v0);
        }
    }
    for (; i < c; i++) {
        if (lane < C8) {
            uint4 v0 = ((const uint4*)(x + (size_t)bk[i] * STR))[lane];
            hmax4_acc(m, v0);
        }
    }

    if (lane < C8) {
        uint4 z = make_uint4(0u, 0u, 0u, 0u);
        ((uint4*)(o + (size_t)gwarp * STR))[lane] = (c == 0) ? z : m;
    }
}

// ---------------- plain fp16 tensor-core dual GEMM ---------------------------
#define MMAF16(d, a, b0, b1)                                                  \
    asm volatile(                                                             \
        "mma.sync.aligned.m16n8k16.row.col.f32.f16.f16.f32 "                  \
        "{%0,%1,%2,%3}, {%4,%5,%6,%7}, {%8,%9}, {%0,%1,%2,%3};"               \
        : "+f"(d[0]), "+f"(d[1]), "+f"(d[2]), "+f"(d[3])                      \
        : "r"(a[0]), "r"(a[1]), "r"(a[2]), "r"(a[3]), "r"(b0), "r"(b1))

// out = (A1@W1 + A2@W2 + bias) as fp16 rows of stride ostride.
// BM=128 (WM=4), BN=WN*NT*8, 256 threads, ST-stage cp.async, ldmatrix frags.
template <int WN, int NT, int OCC, int KB, int ST>
__global__ __launch_bounds__(256, OCC)
void gemm_s(const h16* __restrict__ A1, const h16* __restrict__ A2,
            const h16* __restrict__ B1, const h16* __restrict__ B2,
            const float* __restrict__ bias,
            h16* __restrict__ outh,
            int M, int K, int NN, int ostride) {
    constexpr int WM = 4;
    constexpr int BM = 128;
    constexpr int BN = WN * NT * 8;
    constexpr int LDSTR = KB + 8;
    constexpr int NC = KB / 16;
    static_assert(WM * WN == 8 && NT % 2 == 0, "bad tile config");

    extern __shared__ __align__(16) char smem_raw[];
    h16* Ash = (h16*)smem_raw;                  // ST * BM * LDSTR
    h16* Bsh = Ash + ST * BM * LDSTR;           // ST * BN * LDSTR

    int tid = threadIdx.x;
    int lane = tid & 31;
    int wid = tid >> 5;
    int wm = wid % WM;
    int wn = wid / WM;
    int g  = lane >> 2;
    int tg = lane & 3;
    int lr = lane & 15;
    int lc = (lane >> 4) * 8;

    int rowBase = blockIdx.y * BM;
    int colBase = blockIdx.x * BN;

    int npt  = K / KB;
    int totT = 2 * npt;

    const int r_  = tid >> 1;
    const int kh_ = (tid & 1) * (KB / 2);
    const int aRow = rowBase + r_;
    const bool doB = r_ < BN;
    const int gN   = colBase + r_;

    float acc[2][NT][4];
#pragma unroll
    for (int mt = 0; mt < 2; mt++)
#pragma unroll
        for (int nt = 0; nt < NT; nt++)
#pragma unroll
            for (int q = 0; q < 4; q++) acc[mt][nt][q] = 0.f;

    auto issue = [&](int t, int s) {
        const h16 *A, *B; int ko;
        if (t < npt) { A = A1; B = B1; ko = t * KB; }
        else         { A = A2; B = B2; ko = (t - npt) * KB; }
        int gk = ko + kh_;
        bool okA = aRow < M;
#pragma unroll
        for (int cc = 0; cc < NC; cc++)
            cp16(&Ash[s * BM * LDSTR + r_ * LDSTR + kh_ + cc * 8],
                 okA ? (A + (size_t)aRow * K + gk + cc * 8) : A, okA);
        if (doB) {
            bool okB = gN < NN;
#pragma unroll
            for (int cc = 0; cc < NC; cc++)
                cp16(&Bsh[s * BN * LDSTR + r_ * LDSTR + kh_ + cc * 8],
                     okB ? (B + (size_t)gN * K + gk + cc * 8) : B, okB);
        }
    };

    auto compute = [&](int s) {
        const h16* As = Ash + s * BM * LDSTR;
        const h16* Bs = Bsh + s * BN * LDSTR;

#pragma unroll
        for (int ks = 0; ks < NC; ks++) {
            int kc = lc + ks * 16;
            unsigned af[2][4];
#pragma unroll
            for (int mt = 0; mt < 2; mt++) {
                int r0 = wm * 32 + mt * 16 + lr;
                LDSM_X4(af[mt][0], af[mt][1], af[mt][2], af[mt][3],
                        sptr(&As[r0 * LDSTR + kc]));
            }
#pragma unroll
            for (int p = 0; p < NT / 2; p++) {
                int rowb = (wn * NT + 2 * p) * 8 + lr;
                unsigned b0, b1, b2, b3;
                LDSM_X4(b0, b1, b2, b3, sptr(&Bs[rowb * LDSTR + kc]));
                MMAF16(acc[0][2 * p],     af[0], b0, b2);
                MMAF16(acc[1][2 * p],     af[1], b0, b2);
                MMAF16(acc[0][2 * p + 1], af[0], b1, b3);
                MMAF16(acc[1][2 * p + 1], af[1], b1, b3);
            }
        }
    };

    // prologue: fill ST-1 stages
#pragma unroll
    for (int pt = 0; pt < ST - 1; pt++) {
        if (pt < totT) issue(pt, pt);
        cp_commit();
    }

    for (int t = 0; t < totT; t++) {
        cp_wait<ST - 2>();
        __syncthreads();
        if (t + ST - 1 < totT) issue(t + ST - 1, (t + ST - 1) % ST);
        cp_commit();
        compute(t % ST);
    }

    // ---- epilogue: bias add, fp16 store ----
#pragma unroll
    for (int mt = 0; mt < 2; mt++) {
#pragma unroll
        for (int nt = 0; nt < NT; nt++) {
            int col = colBase + (wn * NT + nt) * 8 + 2 * tg;
            if (col >= NN) continue;
            float2 bv = *(const float2*)(bias + col);
            int row0 = rowBase + wm * 32 + mt * 16 + g;
            int row1 = row0 + 8;
            if (row0 < M)
                *(unsigned*)(outh + (size_t)row0 * ostride + col) =
                    packh2(__float2half_rn(acc[mt][nt][0] + bv.x),
                           __float2half_rn(acc[mt][nt][1] + bv.y));
            if (row1 < M)
                *(unsigned*)(outh + (size_t)row1 * ostride + col) =
                    packh2(__float2half_rn(acc[mt][nt][2] + bv.x),
                           __float2half_rn(acc[mt][nt][3] + bv.y));
        }
    }
}

// ---------------- final layer + log_softmax (fp16 inputs) --------------------
__global__ void final_kernel(const h16* __restrict__ agg,
                             const h16* __restrict__ h,
                             const float* __restrict__ Wl,
                             const float* __restrict__ Wr,
                             const float* __restrict__ b,
                             float* __restrict__ out) {
    __shared__ float sWl[H2 * C_OUT], sWr[H2 * C_OUT], sb[C_OUT];
    for (int i = threadIdx.x; i < H2 * C_OUT; i += blockDim.x) {
        sWl[i] = Wl[i];
        sWr[i] = Wr[i];
    }
    if (threadIdx.x < C_OUT) sb[threadIdx.x] = b[threadIdx.x];
    __syncthreads();

    int n = blockIdx.x * blockDim.x + threadIdx.x;
    if (n >= N_NODES) return;

    float logit[C_OUT];
#pragma unroll
    for (int j = 0; j < C_OUT; j++) logit[j] = sb[j];

    const h16* ar = agg + (size_t)n * H2P;
    const h16* hr = h   + (size_t)n * H2P;
#pragma unroll 5
    for (int k = 0; k < H2; k++) {
        float a  = __half2float(ar[k]);
        float hh = __half2float(hr[k]);
#pragma unroll
        for (int j = 0; j < C_OUT; j++)
            logit[j] += a * sWl[k * C_OUT + j] + hh * sWr[k * C_OUT + j];
    }

    float mx = logit[0];
#pragma unroll
    for (int j = 1; j < C_OUT; j++) mx = fmaxf(mx, logit[j]);
    float s = 0.0f;
#pragma unroll
    for (int j = 0; j < C_OUT; j++) s += expf(logit[j] - mx);
    float lse = mx + logf(s);
#pragma unroll
    for (int j = 0; j < C_OUT; j++) out[(size_t)n * C_OUT + j] = logit[j] - lse;
}

// ---------------- launch ------------------------------------------------------
extern "C" void kernel_launch(void* const* d_in, const int* in_sizes, int n_in,
                              void* d_out, int out_size) {
    const float* x    = (const float*)d_in[0];
    const int*   ei   = (const int*)d_in[1];
    const float* W_l1 = (const float*)d_in[2];
    const float* b1   = (const float*)d_in[3];
    const float* W_r1 = (const float*)d_in[4];
    const float* W_l2 = (const float*)d_in[5];
    const float* b2   = (const float*)d_in[6];
    const float* W_r2 = (const float*)d_in[7];
    const float* W_l3 = (const float*)d_in[8];
    const float* b3   = (const float*)d_in[9];
    const float* W_r3 = (const float*)d_in[10];
    float* out = (float*)d_out;

    const int* src = ei;
    const int* dst = ei + N_EDGES;

    h16 *xh, *a1h, *h1h, *a2h, *h2h, *a3h, *w1l, *w1r, *w2l, *w2r;
    cudaGetSymbolAddress((void**)&xh,  g_xh);
    cudaGetSymbolAddress((void**)&a1h, g_a1h);
    cudaGetSymbolAddress((void**)&h1h, g_h1h);
    cudaGetSymbolAddress((void**)&a2h, g_a2h);
    cudaGetSymbolAddress((void**)&h2h, g_h2h);
    cudaGetSymbolAddress((void**)&a3h, g_a3h);
    cudaGetSymbolAddress((void**)&w1l, g_w1l);
    cudaGetSymbolAddress((void**)&w1r, g_w1r);
    cudaGetSymbolAddress((void**)&w2l, g_w2l);
    cudaGetSymbolAddress((void**)&w2r, g_w2r);

    // smem: ST * (BM + BN) * (KB+8) * 2 bytes
    const int SMEM1 = 4 * (128 + 128) * 40 * 2;   // 81920 (KB=32, ST=4)
    const int SMEM2 = 3 * (128 + 64) * 24 * 2;    // 27648 (KB=16, ST=3)
    cudaFuncSetAttribute(gemm_s<2, 8, 2, 32, 4>,
                         cudaFuncAttributeMaxDynamicSharedMemorySize, SMEM1);
    cudaFuncSetAttribute(gemm_s<2, 4, 3, 16, 3>,
                         cudaFuncAttributeMaxDynamicSharedMemorySize, SMEM2);

    prep_kernel<<<(N_NODES * F_IN / 4 + 255) / 256, 256>>>(x, W_l1, W_r1,
                                                           W_l2, W_r2);
    bucket_build_kernel<<<(N_EDGES + 255) / 256, 256>>>(src, dst);

    const int aggBlocks = (N_NODES * 32 + 255) / 256;

    // layer 1: agg over xh -> a1h; GEMM (BM=128, BN=128, KB=32, ST=4) -> h1h
    agg_h16_kernel<F_IN, F_IN><<<aggBlocks, 256>>>(xh, a1h);
    {
        dim3 grid((H1 + 127) / 128, (N_NODES + 127) / 128);
        gemm_s<2, 8, 2, 32, 4><<<grid, 256, SMEM1>>>(
            a1h, xh, w1l, w1r, b1, h1h, N_NODES, F_IN, H1, H1P);
    }

    // layer 2: agg over h1h (uint4 gather) -> a2h; GEMM (BM=128, BN=64) -> h2h
    agg_h16x4_kernel<H1P, H1P><<<aggBlocks, 256>>>(h1h, a2h);
    {
        dim3 grid(1, (N_NODES + 127) / 128);
        gemm_s<2, 4, 3, 16, 3><<<grid, 256, SMEM2>>>(
            a2h, h1h, w2l, w2r, b2, h2h, N_NODES, H1P, H2, H2P);
    }

    // layer 3: agg over h2h -> a3h; final matvec + log_softmax
    agg_h16_kernel<H2P, H2P><<<aggBlocks, 256>>>(h2h, a3h);
    final_kernel<<<(N_NODES + 255) / 256, 256>>>(a3h, h2h, W_l3, W_r3, b3, out);
}